// round 11
// baseline (speedup 1.0000x reference)
#include <cuda_runtime.h>
#include <cuda_fp16.h>
#include <cstdint>

// Problem constants
#define N_NODES 100000
#define N_PAD   100096          // 782 * 128
#define NBINS   400000          // 4 * N_NODES
#define NT2     400384          // bins padded to 391*1024
#define NBLK2   391             // NT2 / 1024
#define D 128
#define N_REL 4
#define N_EDGES 500000
#define TOT_E   (N_REL * N_EDGES)   // 2,000,000

// Device scratch (globals; zero-initialized at load; no runtime allocation)
__device__ __half g_Xs[(size_t)N_PAD * 128];         // x rows fp16 (padded)
__device__ __half g_Wx[(size_t)128 * 640];           // [W0|W1|W2|W3|Wsl] per out-feature row
__device__ int g_cnt[NT2];
__device__ int g_off[NT2];
__device__ int g_cursor[NT2];
__device__ int g_part[NBLK2];
__device__ int g_payload[TOT_E];                     // src node per sorted edge

// ---------------------------------------------------------------------------
// helpers
// ---------------------------------------------------------------------------
__device__ __forceinline__ uint32_t smem_u32(const void* p) {
    uint32_t a;
    asm("{ .reg .u64 t; cvta.to.shared.u64 t, %1; cvt.u32.u64 %0, t; }" : "=r"(a) : "l"(p));
    return a;
}
__device__ __forceinline__ void ldsm_x4(uint32_t addr, uint32_t& r0, uint32_t& r1,
                                        uint32_t& r2, uint32_t& r3) {
    asm volatile("ldmatrix.sync.aligned.m8n8.x4.shared.b16 {%0,%1,%2,%3}, [%4];"
                 : "=r"(r0), "=r"(r1), "=r"(r2), "=r"(r3) : "r"(addr));
}
__device__ __forceinline__ void mma16816(float* c, uint32_t a0, uint32_t a1, uint32_t a2,
                                         uint32_t a3, uint32_t b0, uint32_t b1) {
    asm volatile("mma.sync.aligned.m16n8k16.row.col.f32.f16.f16.f32 "
                 "{%0,%1,%2,%3}, {%4,%5,%6,%7}, {%8,%9}, {%0,%1,%2,%3};"
                 : "+f"(c[0]), "+f"(c[1]), "+f"(c[2]), "+f"(c[3])
                 : "r"(a0), "r"(a1), "r"(a2), "r"(a3), "r"(b0), "r"(b1));
}
__device__ __forceinline__ void cp16(uint32_t smem_dst, const void* gsrc) {
    asm volatile("cp.async.cg.shared.global [%0], [%1], 16;"
                 :: "r"(smem_dst), "l"(gsrc));
}

// ---------------------------------------------------------------------------
// conv_x: fp32 x -> fp16 g_Xs rows
// ---------------------------------------------------------------------------
__global__ __launch_bounds__(256) void conv_x_kernel(const float* __restrict__ x) {
    size_t i = (size_t)blockIdx.x * blockDim.x + threadIdx.x;
    if (i >= (size_t)N_NODES * 32) return;
    size_t row = i >> 5;
    int c4 = (int)(i & 31);
    float4 v = reinterpret_cast<const float4*>(x)[i];
    __half h[4];
    h[0] = __float2half_rn(v.x); h[1] = __float2half_rn(v.y);
    h[2] = __float2half_rn(v.z); h[3] = __float2half_rn(v.w);
    *reinterpret_cast<uint2*>(&g_Xs[row * 128 + c4 * 4]) = *reinterpret_cast<uint2*>(h);
}

// conv_w: g_Wx[f][0..639] = [W0[f]|W1[f]|W2[f]|W3[f]|Wsl[f]] fp16
__global__ __launch_bounds__(256) void conv_w_kernel(const float* __restrict__ W,
                                                     const float* __restrict__ Wsl) {
    int i = blockIdx.x * blockDim.x + threadIdx.x;
    if (i >= 128 * 160) return;
    int f = i / 160;
    int c = (i - f * 160) * 4;
    float4 v;
    if (c < 512) {
        int r = c >> 7, dd = c & 127;
        v = *reinterpret_cast<const float4*>(W + (size_t)r * 16384 + (size_t)f * 128 + dd);
    } else {
        v = *reinterpret_cast<const float4*>(Wsl + (size_t)f * 128 + (c - 512));
    }
    __half h[4];
    h[0] = __float2half_rn(v.x); h[1] = __float2half_rn(v.y);
    h[2] = __float2half_rn(v.z); h[3] = __float2half_rn(v.w);
    *reinterpret_cast<uint2*>(&g_Wx[(size_t)f * 640 + c]) = *reinterpret_cast<uint2*>(h);
}

// ---------------------------------------------------------------------------
// Counting sort by key = tgt*4 + rel  (vectorized, 4 edges/thread)
// ---------------------------------------------------------------------------
__global__ __launch_bounds__(256) void zero_cnt_kernel() {
    int i = blockIdx.x * blockDim.x + threadIdx.x;
    if (i < NT2 / 4)
        reinterpret_cast<int4*>(g_cnt)[i] = make_int4(0, 0, 0, 0);
}

__global__ __launch_bounds__(256) void hist_kernel(const int* __restrict__ EI) {
    int i = blockIdx.x * blockDim.x + threadIdx.x;
    if (i >= TOT_E / 4) return;
    int gq = i * 4;
    int r = gq / N_EDGES;
    int e = gq - r * N_EDGES;
    int4 tg = *reinterpret_cast<const int4*>(EI + (size_t)r * 2 * N_EDGES + N_EDGES + e);
    atomicAdd(&g_cnt[tg.x * 4 + r], 1);
    atomicAdd(&g_cnt[tg.y * 4 + r], 1);
    atomicAdd(&g_cnt[tg.z * 4 + r], 1);
    atomicAdd(&g_cnt[tg.w * 4 + r], 1);
}

__global__ __launch_bounds__(256) void scan_part_kernel() {
    __shared__ int s[256];
    int b = blockIdx.x, t = threadIdx.x;
    int4 v4 = reinterpret_cast<const int4*>(g_cnt)[b * 256 + t];
    s[t] = v4.x + v4.y + v4.z + v4.w;
    __syncthreads();
    for (int off = 128; off > 0; off >>= 1) {
        if (t < off) s[t] += s[t + off];
        __syncthreads();
    }
    if (t == 0) g_part[b] = s[0];
}

__global__ __launch_bounds__(256) void scan_final_kernel() {
    __shared__ int parts[NBLK2];
    __shared__ int s[256];
    int b = blockIdx.x, t = threadIdx.x;
    for (int i = t; i < NBLK2; i += 256) parts[i] = g_part[i];
    __syncthreads();
    int pp = 0;
    for (int i = t; i < b; i += 256) pp += parts[i];
    s[t] = pp;
    __syncthreads();
    for (int off = 128; off > 0; off >>= 1) {
        if (t < off) s[t] += s[t + off];
        __syncthreads();
    }
    const int blockbase = s[0];
    __syncthreads();

    int base = b * 1024 + t * 4;
    int4 e4 = *reinterpret_cast<const int4*>(g_cnt + base);
    int e[4] = {e4.x, e4.y, e4.z, e4.w};
    int local[4], sum = 0;
#pragma unroll
    for (int j = 0; j < 4; j++) { local[j] = sum; sum += e[j]; }
    s[t] = sum;
    __syncthreads();
    int own = sum;
    for (int d = 1; d < 256; d <<= 1) {
        int add = (t >= d) ? s[t - d] : 0;
        __syncthreads();
        s[t] += add;
        __syncthreads();
    }
    int baseoff = blockbase + (s[t] - own);
    int4 o4 = make_int4(baseoff + local[0], baseoff + local[1],
                        baseoff + local[2], baseoff + local[3]);
    *reinterpret_cast<int4*>(g_off + base) = o4;
    *reinterpret_cast<int4*>(g_cursor + base) = o4;
}

__global__ __launch_bounds__(256) void reorder_kernel(const int* __restrict__ EI) {
    int i = blockIdx.x * blockDim.x + threadIdx.x;
    if (i >= TOT_E / 4) return;
    int gq = i * 4;
    int r = gq / N_EDGES;
    int e = gq - r * N_EDGES;
    const int* base = EI + (size_t)r * 2 * N_EDGES;
    int4 sr = *reinterpret_cast<const int4*>(base + e);
    int4 tg = *reinterpret_cast<const int4*>(base + N_EDGES + e);
    g_payload[atomicAdd(&g_cursor[tg.x * 4 + r], 1)] = sr.x;
    g_payload[atomicAdd(&g_cursor[tg.y * 4 + r], 1)] = sr.y;
    g_payload[atomicAdd(&g_cursor[tg.z * 4 + r], 1)] = sr.z;
    g_payload[atomicAdd(&g_cursor[tg.w * 4 + r], 1)] = sr.w;
}

// ---------------------------------------------------------------------------
// FUSED gather+GEMM. CTA = 128 nodes. 5 phases of K=128:
//   phase r<4: gather bins (t, r) directly into swizzled SMEM A-tile (fp16),
//              B tiles for this phase stream in via cp.async underneath;
//   phase 4:   cp.async x-rows tile.
// After each phase: 2 x 64-col K-steps of ldmatrix+mma.
// SMEM: A 32KB | B 32KB | counts 2KB.
// ---------------------------------------------------------------------------
__global__ __launch_bounds__(256, 2) void fused_kernel(const float* __restrict__ b,
                                                       const float* __restrict__ bsl,
                                                       float* __restrict__ out) {
    extern __shared__ __half smem[];
    char* sm = reinterpret_cast<char*>(smem);
    const uint32_t sAu = smem_u32(sm);          // [0, 32768): 2 subtiles of 16KB
    const uint32_t sBu = sAu + 32768;           // [32768, 65536): 2 tiles of 16KB
    float* sc = reinterpret_cast<float*>(sm + 65536);   // 512 floats

    const int tid = threadIdx.x;
    const int lane = tid & 31;
    const int wid = tid >> 5;
    const int wm = wid & 3;
    const int wn = wid >> 2;
    const int m0 = blockIdx.x * 128;

    float acc[2][8][4];
#pragma unroll
    for (int i = 0; i < 2; i++)
#pragma unroll
        for (int j = 0; j < 8; j++)
#pragma unroll
            for (int k = 0; k < 4; k++) acc[i][j][k] = 0.0f;

#pragma unroll 1
    for (int phase = 0; phase < 5; phase++) {
        // Issue cp.async for this phase's two B tiles (overlaps with gather below)
#pragma unroll
        for (int it = 0; it < 8; it++) {
            int idx = tid + it * 256;            // 0..2047
            int tile = idx >> 10;
            int rr = (idx >> 3) & 127;
            int ch = idx & 7;
            int kc = (phase * 2 + tile) * 64;
            cp16(sBu + tile * 16384 + rr * 128 + ((ch ^ (rr & 7)) << 4),
                 g_Wx + (size_t)rr * 640 + kc + ch * 8);
        }
        if (phase == 4) {
            // x-rows A tile via cp.async
#pragma unroll
            for (int it = 0; it < 8; it++) {
                int idx = tid + it * 256;        // 0..2047
                int rr = idx >> 4;
                int ch = idx & 15;
                cp16(sAu + (ch >> 3) * 16384 + rr * 128 + (((ch & 7) ^ (rr & 7)) << 4),
                     g_Xs + (size_t)(m0 + rr) * 128 + ch * 8);
            }
        }
        asm volatile("cp.async.commit_group;");

        if (phase < 4) {
            const int r = phase;
            const int group = lane >> 4;
            const int sub = lane & 15;
            for (int bi = wid; bi < 128; bi += 8) {
                int t = m0 + bi;
                int beg = 0, end = 0;
                if (t < N_NODES) {
                    int k = t * 4 + r;
                    beg = g_off[k];
                    end = g_off[k + 1];
                }
                float a8[8];
#pragma unroll
                for (int q = 0; q < 8; q++) a8[q] = 0.0f;

                for (int base = beg; base < end; base += 32) {
                    int i = base + lane;
                    int p = (i < end) ? g_payload[i] : 0;
                    int mm = min(end - base, 32);
                    for (int j = 0; j < mm; j += 2) {
                        int jj = j + group;
                        int src = __shfl_sync(0xffffffffu, p, min(jj, mm - 1));
                        if (jj < mm) {
                            uint4 raw = *reinterpret_cast<const uint4*>(
                                g_Xs + (size_t)src * 128 + sub * 8);
                            const __half2* h2 = reinterpret_cast<const __half2*>(&raw);
#pragma unroll
                            for (int q = 0; q < 4; q++) {
                                float2 f = __half22float2(h2[q]);
                                a8[q * 2 + 0] += f.x;
                                a8[q * 2 + 1] += f.y;
                            }
                        }
                    }
                }
#pragma unroll
                for (int q = 0; q < 8; q++)
                    a8[q] += __shfl_xor_sync(0xffffffffu, a8[q], 16);

                if (group == 0) {
                    __half h[8];
#pragma unroll
                    for (int q = 0; q < 8; q++) h[q] = __float2half_rn(a8[q]);
                    *reinterpret_cast<uint4*>(
                        sm + (sub >> 3) * 16384 + bi * 128 + (((sub & 7) ^ (bi & 7)) << 4)) =
                        *reinterpret_cast<uint4*>(h);
                }
                if (lane == 0) sc[bi * 4 + r] = (float)(end - beg);
            }
        }

        asm volatile("cp.async.wait_group 0;");
        __syncthreads();

        // 2 x 64-col K-steps of MMA from (sA subtile, sB tile)
#pragma unroll
        for (int tile = 0; tile < 2; tile++) {
            const int aoff = tile * 16384;
            const int boff = tile * 16384;
#pragma unroll
            for (int kq = 0; kq < 4; kq++) {
                uint32_t a[2][4];
#pragma unroll
                for (int mf = 0; mf < 2; mf++) {
                    int row = wm * 32 + mf * 16 + (lane & 15);
                    int kch = kq * 2 + (lane >> 4);
                    uint32_t addr = sAu + aoff + row * 128 + ((kch ^ (row & 7)) << 4);
                    ldsm_x4(addr, a[mf][0], a[mf][1], a[mf][2], a[mf][3]);
                }
                uint32_t bb[8][2];
#pragma unroll
                for (int np = 0; np < 4; np++) {
                    int n = wn * 64 + np * 16 + ((lane >> 4) << 3) + (lane & 7);
                    int kch = kq * 2 + ((lane >> 3) & 1);
                    uint32_t addr = sBu + boff + n * 128 + ((kch ^ (n & 7)) << 4);
                    ldsm_x4(addr, bb[np * 2][0], bb[np * 2][1],
                            bb[np * 2 + 1][0], bb[np * 2 + 1][1]);
                }
#pragma unroll
                for (int mf = 0; mf < 2; mf++)
#pragma unroll
                    for (int nf = 0; nf < 8; nf++)
                        mma16816(acc[mf][nf], a[mf][0], a[mf][1], a[mf][2], a[mf][3],
                                 bb[nf][0], bb[nf][1]);
            }
        }
        __syncthreads();   // before next phase overwrites sA/sB
    }

    // Epilogue: + Sum_r c4[r]*b[r][col] + bsl[col]; single write of out.
    const int r0 = lane >> 2;
    const int c0 = (lane & 3) * 2;
#pragma unroll
    for (int mf = 0; mf < 2; mf++) {
#pragma unroll
        for (int half = 0; half < 2; half++) {
            int rl = wm * 32 + mf * 16 + r0 + half * 8;   // row within tile
            int gm = m0 + rl;
            if (gm >= N_NODES) continue;
            float4 c4 = *reinterpret_cast<const float4*>(sc + rl * 4);
            float* dst = out + (size_t)gm * 128 + wn * 64 + c0;
#pragma unroll
            for (int nf = 0; nf < 8; nf++) {
                int col = wn * 64 + c0 + nf * 8;
                float2 b0 = *reinterpret_cast<const float2*>(b + 0 * 128 + col);
                float2 b1 = *reinterpret_cast<const float2*>(b + 1 * 128 + col);
                float2 b2 = *reinterpret_cast<const float2*>(b + 2 * 128 + col);
                float2 b3 = *reinterpret_cast<const float2*>(b + 3 * 128 + col);
                float2 bs = *reinterpret_cast<const float2*>(bsl + col);
                float2 v;
                v.x = acc[mf][nf][half * 2] +
                      c4.x * b0.x + c4.y * b1.x + c4.z * b2.x + c4.w * b3.x + bs.x;
                v.y = acc[mf][nf][half * 2 + 1] +
                      c4.x * b0.y + c4.y * b1.y + c4.z * b2.y + c4.w * b3.y + bs.y;
                *reinterpret_cast<float2*>(dst + nf * 8) = v;
            }
        }
    }
}

// ---------------------------------------------------------------------------
extern "C" void kernel_launch(void* const* d_in, const int* in_sizes, int n_in,
                              void* d_out, int out_size) {
    const float* x   = (const float*)d_in[0];
    const int*   ei  = (const int*)  d_in[1];
    const float* W   = (const float*)d_in[2];
    const float* b   = (const float*)d_in[3];
    const float* Wsl = (const float*)d_in[4];
    const float* bsl = (const float*)d_in[5];
    float* out = (float*)d_out;

    const int FUSED_SMEM = 65536 + 2048;   // A(32K) + B(32K) + counts(2K)

    static cudaStream_t s2 = nullptr;
    static cudaEvent_t ev_fork = nullptr, ev_join = nullptr;
    static bool overlap_ok = false;
    static bool attr_done = false;
    if (!attr_done) {
        cudaFuncSetAttribute(fused_kernel,
                             cudaFuncAttributeMaxDynamicSharedMemorySize, FUSED_SMEM);
        attr_done = true;
    }
    if (!s2) {
        overlap_ok =
            (cudaStreamCreateWithFlags(&s2, cudaStreamNonBlocking) == cudaSuccess) &&
            (cudaEventCreateWithFlags(&ev_fork, cudaEventDisableTiming) == cudaSuccess) &&
            (cudaEventCreateWithFlags(&ev_join, cudaEventDisableTiming) == cudaSuccess);
    }

    if (!overlap_ok) {
        conv_x_kernel<<<(N_NODES * 32 + 255) / 256, 256>>>(x);
        conv_w_kernel<<<(128 * 160 + 255) / 256, 256>>>(W, Wsl);
        zero_cnt_kernel<<<(NT2 / 4 + 255) / 256, 256>>>();
        hist_kernel<<<(TOT_E / 4 + 255) / 256, 256>>>(ei);
        scan_part_kernel<<<NBLK2, 256>>>();
        scan_final_kernel<<<NBLK2, 256>>>();
        reorder_kernel<<<(TOT_E / 4 + 255) / 256, 256>>>(ei);
        fused_kernel<<<782, 256, FUSED_SMEM>>>(b, bsl, out);
        return;
    }

    // fork
    cudaEventRecord(ev_fork, 0);
    cudaStreamWaitEvent(s2, ev_fork, 0);

    // Stream 0: conversions (fused kernel needs g_Xs, g_Wx)
    conv_x_kernel<<<(N_NODES * 32 + 255) / 256, 256>>>(x);
    conv_w_kernel<<<(128 * 160 + 255) / 256, 256>>>(W, Wsl);

    // Stream B: counting sort (independent of conversions)
    zero_cnt_kernel<<<(NT2 / 4 + 255) / 256, 256, 0, s2>>>();
    hist_kernel<<<(TOT_E / 4 + 255) / 256, 256, 0, s2>>>(ei);
    scan_part_kernel<<<NBLK2, 256, 0, s2>>>();
    scan_final_kernel<<<NBLK2, 256, 0, s2>>>();
    reorder_kernel<<<(TOT_E / 4 + 255) / 256, 256, 0, s2>>>(ei);
    cudaEventRecord(ev_join, s2);

    // Stream 0: fused gather+GEMM after sort (conv already ordered on stream 0)
    cudaStreamWaitEvent(0, ev_join, 0);
    fused_kernel<<<782, 256, FUSED_SMEM, 0>>>(b, bsl, out);
}

// round 12
// speedup vs baseline: 1.3813x; 1.3813x over previous
#include <cuda_runtime.h>
#include <cuda_fp16.h>
#include <cstdint>

// Problem constants
#define N_NODES 100000
#define N_PAD   100096          // 782 * 128
#define NBINS   400000          // 4 * N_NODES
#define NT2     400384          // bins padded to 391*1024
#define NBLK2   391             // NT2 / 1024
#define D 128
#define N_REL 4
#define N_EDGES 500000
#define TOT_E   (N_REL * N_EDGES)   // 2,000,000
#define KROW    512             // S row: [S0|S1|S2|S3] halves (x handled separately)

// Device scratch (globals; zero-initialized at load; no runtime allocation)
__device__ __half g_Xs[(size_t)N_PAD * 128];         // x rows fp16 (padded)
__device__ __half g_S[(size_t)N_PAD * KROW];         // aggregated features per node (102MB)
__device__ __half g_Wx[(size_t)128 * 640];           // [W0|W1|W2|W3|Wsl] per out-feature row
__device__ float g_C4[NBINS];                        // per-(node,rel) edge counts
__device__ int g_cnt[NT2];
__device__ int g_off[NT2];
__device__ int g_cursor[NT2];
__device__ int g_part[NBLK2];
__device__ int g_payload[TOT_E];                     // src node per sorted edge

// ---------------------------------------------------------------------------
// helpers
// ---------------------------------------------------------------------------
__device__ __forceinline__ uint32_t smem_u32(const void* p) {
    uint32_t a;
    asm("{ .reg .u64 t; cvta.to.shared.u64 t, %1; cvt.u32.u64 %0, t; }" : "=r"(a) : "l"(p));
    return a;
}
__device__ __forceinline__ void ldsm_x4(uint32_t addr, uint32_t& r0, uint32_t& r1,
                                        uint32_t& r2, uint32_t& r3) {
    asm volatile("ldmatrix.sync.aligned.m8n8.x4.shared.b16 {%0,%1,%2,%3}, [%4];"
                 : "=r"(r0), "=r"(r1), "=r"(r2), "=r"(r3) : "r"(addr));
}
__device__ __forceinline__ void mma16816(float* c, uint32_t a0, uint32_t a1, uint32_t a2,
                                         uint32_t a3, uint32_t b0, uint32_t b1) {
    asm volatile("mma.sync.aligned.m16n8k16.row.col.f32.f16.f16.f32 "
                 "{%0,%1,%2,%3}, {%4,%5,%6,%7}, {%8,%9}, {%0,%1,%2,%3};"
                 : "+f"(c[0]), "+f"(c[1]), "+f"(c[2]), "+f"(c[3])
                 : "r"(a0), "r"(a1), "r"(a2), "r"(a3), "r"(b0), "r"(b1));
}
__device__ __forceinline__ void cp16(uint32_t smem_dst, const void* gsrc) {
    asm volatile("cp.async.cg.shared.global [%0], [%1], 16;"
                 :: "r"(smem_dst), "l"(gsrc));
}

// ---------------------------------------------------------------------------
// conv_x: fp32 x -> fp16 g_Xs rows
// ---------------------------------------------------------------------------
__global__ __launch_bounds__(256) void conv_x_kernel(const float* __restrict__ x) {
    size_t i = (size_t)blockIdx.x * blockDim.x + threadIdx.x;
    if (i >= (size_t)N_NODES * 32) return;
    size_t row = i >> 5;
    int c4 = (int)(i & 31);
    float4 v = reinterpret_cast<const float4*>(x)[i];
    __half h[4];
    h[0] = __float2half_rn(v.x); h[1] = __float2half_rn(v.y);
    h[2] = __float2half_rn(v.z); h[3] = __float2half_rn(v.w);
    *reinterpret_cast<uint2*>(&g_Xs[row * 128 + c4 * 4]) = *reinterpret_cast<uint2*>(h);
}

// conv_w: g_Wx[f][0..639] = [W0[f]|W1[f]|W2[f]|W3[f]|Wsl[f]] fp16
__global__ __launch_bounds__(256) void conv_w_kernel(const float* __restrict__ W,
                                                     const float* __restrict__ Wsl) {
    int i = blockIdx.x * blockDim.x + threadIdx.x;
    if (i >= 128 * 160) return;
    int f = i / 160;
    int c = (i - f * 160) * 4;
    float4 v;
    if (c < 512) {
        int r = c >> 7, dd = c & 127;
        v = *reinterpret_cast<const float4*>(W + (size_t)r * 16384 + (size_t)f * 128 + dd);
    } else {
        v = *reinterpret_cast<const float4*>(Wsl + (size_t)f * 128 + (c - 512));
    }
    __half h[4];
    h[0] = __float2half_rn(v.x); h[1] = __float2half_rn(v.y);
    h[2] = __float2half_rn(v.z); h[3] = __float2half_rn(v.w);
    *reinterpret_cast<uint2*>(&g_Wx[(size_t)f * 640 + c]) = *reinterpret_cast<uint2*>(h);
}

// ---------------------------------------------------------------------------
// Counting sort by key = tgt*4 + rel  (vectorized, 4 edges/thread)
// ---------------------------------------------------------------------------
__global__ __launch_bounds__(256) void zero_cnt_kernel() {
    int i = blockIdx.x * blockDim.x + threadIdx.x;
    if (i < NT2 / 4)
        reinterpret_cast<int4*>(g_cnt)[i] = make_int4(0, 0, 0, 0);
}

__global__ __launch_bounds__(256) void hist_kernel(const int* __restrict__ EI) {
    int i = blockIdx.x * blockDim.x + threadIdx.x;
    if (i >= TOT_E / 4) return;
    int gq = i * 4;
    int r = gq / N_EDGES;
    int e = gq - r * N_EDGES;
    int4 tg = *reinterpret_cast<const int4*>(EI + (size_t)r * 2 * N_EDGES + N_EDGES + e);
    atomicAdd(&g_cnt[tg.x * 4 + r], 1);
    atomicAdd(&g_cnt[tg.y * 4 + r], 1);
    atomicAdd(&g_cnt[tg.z * 4 + r], 1);
    atomicAdd(&g_cnt[tg.w * 4 + r], 1);
}

__global__ __launch_bounds__(256) void scan_part_kernel() {
    __shared__ int s[256];
    int b = blockIdx.x, t = threadIdx.x;
    int4 v4 = reinterpret_cast<const int4*>(g_cnt)[b * 256 + t];
    s[t] = v4.x + v4.y + v4.z + v4.w;
    __syncthreads();
    for (int off = 128; off > 0; off >>= 1) {
        if (t < off) s[t] += s[t + off];
        __syncthreads();
    }
    if (t == 0) g_part[b] = s[0];
}

__global__ __launch_bounds__(256) void scan_final_kernel() {
    __shared__ int parts[NBLK2];
    __shared__ int s[256];
    int b = blockIdx.x, t = threadIdx.x;
    for (int i = t; i < NBLK2; i += 256) parts[i] = g_part[i];
    __syncthreads();
    int pp = 0;
    for (int i = t; i < b; i += 256) pp += parts[i];
    s[t] = pp;
    __syncthreads();
    for (int off = 128; off > 0; off >>= 1) {
        if (t < off) s[t] += s[t + off];
        __syncthreads();
    }
    const int blockbase = s[0];
    __syncthreads();

    int base = b * 1024 + t * 4;
    int4 e4 = *reinterpret_cast<const int4*>(g_cnt + base);
    int e[4] = {e4.x, e4.y, e4.z, e4.w};
    int local[4], sum = 0;
#pragma unroll
    for (int j = 0; j < 4; j++) { local[j] = sum; sum += e[j]; }
    s[t] = sum;
    __syncthreads();
    int own = sum;
    for (int d = 1; d < 256; d <<= 1) {
        int add = (t >= d) ? s[t - d] : 0;
        __syncthreads();
        s[t] += add;
        __syncthreads();
    }
    int baseoff = blockbase + (s[t] - own);
    int4 o4 = make_int4(baseoff + local[0], baseoff + local[1],
                        baseoff + local[2], baseoff + local[3]);
    *reinterpret_cast<int4*>(g_off + base) = o4;
    *reinterpret_cast<int4*>(g_cursor + base) = o4;
}

__global__ __launch_bounds__(256) void reorder_kernel(const int* __restrict__ EI) {
    int i = blockIdx.x * blockDim.x + threadIdx.x;
    if (i >= TOT_E / 4) return;
    int gq = i * 4;
    int r = gq / N_EDGES;
    int e = gq - r * N_EDGES;
    const int* base = EI + (size_t)r * 2 * N_EDGES;
    int4 sr = *reinterpret_cast<const int4*>(base + e);
    int4 tg = *reinterpret_cast<const int4*>(base + N_EDGES + e);
    g_payload[atomicAdd(&g_cursor[tg.x * 4 + r], 1)] = sr.x;
    g_payload[atomicAdd(&g_cursor[tg.y * 4 + r], 1)] = sr.y;
    g_payload[atomicAdd(&g_cursor[tg.z * 4 + r], 1)] = sr.z;
    g_payload[atomicAdd(&g_cursor[tg.w * 4 + r], 1)] = sr.w;
}

// ---------------------------------------------------------------------------
// Gather: one warp per (target,rel) BIN. k = t*4+r. Mean 5 edges/bin.
// Half-warp per edge (16 lanes x 16B). FOUR edges in flight per step:
// two clamped shuffles issued by ALL lanes, two independent uint4 loads
// issued before accumulation (2x MLP vs one pair per step).
// ---------------------------------------------------------------------------
__global__ __launch_bounds__(256) void gather_kernel() {
    const int k = blockIdx.x * 8 + (threadIdx.x >> 5);
    if (k >= NBINS) return;
    const int lane = threadIdx.x & 31;
    const int group = lane >> 4;
    const int sub = lane & 15;

    const int beg = g_off[k];
    const int end = g_off[k + 1];   // k+1 <= NBINS < NT2, offsets monotone

    float acc[8];
#pragma unroll
    for (int i = 0; i < 8; i++) acc[i] = 0.0f;

    for (int base = beg; base < end; base += 32) {
        int i = base + lane;
        int p = (i < end) ? g_payload[i] : 0;
        int m = min(end - base, 32);
        for (int j = 0; j < m; j += 4) {
            int jj0 = j + group;
            int jj1 = j + 2 + group;
            // all lanes execute both shuffles (indices clamped)
            int s0 = __shfl_sync(0xffffffffu, p, min(jj0, m - 1));
            int s1 = __shfl_sync(0xffffffffu, p, min(jj1, m - 1));
            bool v0 = jj0 < m, v1 = jj1 < m;
            uint4 raw0 = make_uint4(0, 0, 0, 0), raw1 = make_uint4(0, 0, 0, 0);
            if (v0) raw0 = *reinterpret_cast<const uint4*>(g_Xs + (size_t)s0 * 128 + sub * 8);
            if (v1) raw1 = *reinterpret_cast<const uint4*>(g_Xs + (size_t)s1 * 128 + sub * 8);
            const __half2* h0 = reinterpret_cast<const __half2*>(&raw0);
            const __half2* h1 = reinterpret_cast<const __half2*>(&raw1);
#pragma unroll
            for (int q = 0; q < 4; q++) {
                float2 f0 = __half22float2(h0[q]);
                float2 f1 = __half22float2(h1[q]);
                acc[q * 2 + 0] += f0.x + f1.x;
                acc[q * 2 + 1] += f0.y + f1.y;
            }
        }
    }
#pragma unroll
    for (int i = 0; i < 8; i++) acc[i] += __shfl_xor_sync(0xffffffffu, acc[i], 16);

    if (group == 0) {
        const int t = k >> 2;
        const int r = k & 3;
        __half h[8];
#pragma unroll
        for (int q = 0; q < 8; q++) h[q] = __float2half_rn(acc[q]);
        *reinterpret_cast<uint4*>(&g_S[(size_t)t * KROW + r * 128 + sub * 8]) =
            *reinterpret_cast<uint4*>(h);
    }
    if (lane == 0) g_C4[k] = (float)(end - beg);
}

// ---------------------------------------------------------------------------
// GEMM (cp.async double-buffered): out = [S|x] @ Wx^T + Sum_r C4*b_r + bsl
// K=640: steps 0..7 read g_S (512 cols), steps 8..9 read g_Xs (128 cols).
// ---------------------------------------------------------------------------
__global__ __launch_bounds__(256, 2) void gemm_mma_kernel(const float* __restrict__ b,
                                                          const float* __restrict__ bsl,
                                                          float* __restrict__ out) {
    extern __shared__ __half smem[];
    const int tid = threadIdx.x;
    const int lane = tid & 31;
    const int wid = tid >> 5;
    const int wm = wid & 3;
    const int wn = wid >> 2;
    const int m0 = blockIdx.x * 128;

    float acc[2][8][4];
#pragma unroll
    for (int i = 0; i < 2; i++)
#pragma unroll
        for (int j = 0; j < 8; j++)
#pragma unroll
            for (int k = 0; k < 4; k++) acc[i][j][k] = 0.0f;

    const uint32_t sAu = smem_u32(smem);
    const uint32_t sBu = sAu + 2 * 16384;

    auto load_tiles = [&](int buf, int step) {
        const int kc = step * 64;
#pragma unroll
        for (int it = 0; it < 4; it++) {
            int idx = tid + it * 256;
            int row = idx >> 3;
            int ch = idx & 7;
            int sw = (ch ^ (row & 7)) << 4;
            const __half* srcA = (kc < 512)
                ? (g_S + (size_t)(m0 + row) * KROW + kc + ch * 8)
                : (g_Xs + (size_t)(m0 + row) * 128 + (kc - 512) + ch * 8);
            cp16(sAu + buf * 16384 + row * 128 + sw, srcA);
            cp16(sBu + buf * 16384 + row * 128 + sw,
                 g_Wx + (size_t)row * 640 + kc + ch * 8);
        }
        asm volatile("cp.async.commit_group;");
    };

    load_tiles(0, 0);

#pragma unroll 1
    for (int step = 0; step < 10; step++) {
        if (step < 9) {
            load_tiles((step + 1) & 1, step + 1);
            asm volatile("cp.async.wait_group 1;");
        } else {
            asm volatile("cp.async.wait_group 0;");
        }
        __syncthreads();

        const int boff = (step & 1) * 16384;
#pragma unroll
        for (int kq = 0; kq < 4; kq++) {
            uint32_t a[2][4];
#pragma unroll
            for (int mf = 0; mf < 2; mf++) {
                int row = wm * 32 + mf * 16 + (lane & 15);
                int kch = kq * 2 + (lane >> 4);
                uint32_t addr = sAu + boff + row * 128 + ((kch ^ (row & 7)) << 4);
                ldsm_x4(addr, a[mf][0], a[mf][1], a[mf][2], a[mf][3]);
            }
            uint32_t bb[8][2];
#pragma unroll
            for (int np = 0; np < 4; np++) {
                int n = wn * 64 + np * 16 + ((lane >> 4) << 3) + (lane & 7);
                int kch = kq * 2 + ((lane >> 3) & 1);
                uint32_t addr = sBu + boff + n * 128 + ((kch ^ (n & 7)) << 4);
                ldsm_x4(addr, bb[np * 2][0], bb[np * 2][1], bb[np * 2 + 1][0], bb[np * 2 + 1][1]);
            }
#pragma unroll
            for (int mf = 0; mf < 2; mf++)
#pragma unroll
                for (int nf = 0; nf < 8; nf++)
                    mma16816(acc[mf][nf], a[mf][0], a[mf][1], a[mf][2], a[mf][3],
                             bb[nf][0], bb[nf][1]);
        }
        __syncthreads();
    }

    const int r0 = lane >> 2;
    const int c0 = (lane & 3) * 2;
#pragma unroll
    for (int mf = 0; mf < 2; mf++) {
#pragma unroll
        for (int half = 0; half < 2; half++) {
            int gm = m0 + wm * 32 + mf * 16 + r0 + half * 8;
            if (gm >= N_NODES) continue;
            float4 c4 = *reinterpret_cast<const float4*>(g_C4 + (size_t)gm * 4);
            float* dst = out + (size_t)gm * 128 + wn * 64 + c0;
#pragma unroll
            for (int nf = 0; nf < 8; nf++) {
                int col = wn * 64 + c0 + nf * 8;
                float2 b0 = *reinterpret_cast<const float2*>(b + 0 * 128 + col);
                float2 b1 = *reinterpret_cast<const float2*>(b + 1 * 128 + col);
                float2 b2 = *reinterpret_cast<const float2*>(b + 2 * 128 + col);
                float2 b3 = *reinterpret_cast<const float2*>(b + 3 * 128 + col);
                float2 bs = *reinterpret_cast<const float2*>(bsl + col);
                float2 v;
                v.x = acc[mf][nf][half * 2] +
                      c4.x * b0.x + c4.y * b1.x + c4.z * b2.x + c4.w * b3.x + bs.x;
                v.y = acc[mf][nf][half * 2 + 1] +
                      c4.x * b0.y + c4.y * b1.y + c4.z * b2.y + c4.w * b3.y + bs.y;
                *reinterpret_cast<float2*>(dst + nf * 8) = v;
            }
        }
    }
}

// ---------------------------------------------------------------------------
extern "C" void kernel_launch(void* const* d_in, const int* in_sizes, int n_in,
                              void* d_out, int out_size) {
    const float* x   = (const float*)d_in[0];
    const int*   ei  = (const int*)  d_in[1];
    const float* W   = (const float*)d_in[2];
    const float* b   = (const float*)d_in[3];
    const float* Wsl = (const float*)d_in[4];
    const float* bsl = (const float*)d_in[5];
    float* out = (float*)d_out;

    const int GEMM_SMEM = 4 * 128 * 64 * (int)sizeof(__half);  // 64 KB

    static cudaStream_t s2 = nullptr;
    static cudaEvent_t ev_fork = nullptr, ev_convx = nullptr, ev_join = nullptr;
    static bool overlap_ok = false;
    static bool attr_done = false;
    if (!attr_done) {
        cudaFuncSetAttribute(gemm_mma_kernel,
                             cudaFuncAttributeMaxDynamicSharedMemorySize, GEMM_SMEM);
        attr_done = true;
    }
    if (!s2) {
        overlap_ok =
            (cudaStreamCreateWithFlags(&s2, cudaStreamNonBlocking) == cudaSuccess) &&
            (cudaEventCreateWithFlags(&ev_fork, cudaEventDisableTiming) == cudaSuccess) &&
            (cudaEventCreateWithFlags(&ev_convx, cudaEventDisableTiming) == cudaSuccess) &&
            (cudaEventCreateWithFlags(&ev_join, cudaEventDisableTiming) == cudaSuccess);
    }

    if (!overlap_ok) {
        conv_x_kernel<<<(N_NODES * 32 + 255) / 256, 256>>>(x);
        conv_w_kernel<<<(128 * 160 + 255) / 256, 256>>>(W, Wsl);
        zero_cnt_kernel<<<(NT2 / 4 + 255) / 256, 256>>>();
        hist_kernel<<<(TOT_E / 4 + 255) / 256, 256>>>(ei);
        scan_part_kernel<<<NBLK2, 256>>>();
        scan_final_kernel<<<NBLK2, 256>>>();
        reorder_kernel<<<(TOT_E / 4 + 255) / 256, 256>>>(ei);
        gather_kernel<<<NBINS / 8, 256>>>();
        gemm_mma_kernel<<<782, 256, GEMM_SMEM>>>(b, bsl, out);
        return;
    }

    // fork
    cudaEventRecord(ev_fork, 0);
    cudaStreamWaitEvent(s2, ev_fork, 0);

    // Stream 0: conversions
    conv_x_kernel<<<(N_NODES * 32 + 255) / 256, 256>>>(x);
    cudaEventRecord(ev_convx, 0);
    conv_w_kernel<<<(128 * 160 + 255) / 256, 256>>>(W, Wsl);

    // Stream B: counting sort, then gather (needs g_Xs)
    zero_cnt_kernel<<<(NT2 / 4 + 255) / 256, 256, 0, s2>>>();
    hist_kernel<<<(TOT_E / 4 + 255) / 256, 256, 0, s2>>>(ei);
    scan_part_kernel<<<NBLK2, 256, 0, s2>>>();
    scan_final_kernel<<<NBLK2, 256, 0, s2>>>();
    reorder_kernel<<<(TOT_E / 4 + 255) / 256, 256, 0, s2>>>(ei);
    cudaStreamWaitEvent(s2, ev_convx, 0);
    gather_kernel<<<NBINS / 8, 256, 0, s2>>>();
    cudaEventRecord(ev_join, s2);

    // Stream 0: single fused GEMM after gather
    cudaStreamWaitEvent(0, ev_join, 0);
    gemm_mma_kernel<<<782, 256, GEMM_SMEM, 0>>>(b, bsl, out);
}

// round 13
// speedup vs baseline: 1.4775x; 1.0697x over previous
#include <cuda_runtime.h>
#include <cuda_fp16.h>
#include <cstdint>

// Problem constants
#define N_NODES 100000
#define N_PAD   100096          // 782 * 128
#define NBINS   400000          // 4 * N_NODES
#define NT2     400384          // bins padded to 391*1024
#define NBLK2   391             // NT2 / 1024
#define D 128
#define N_REL 4
#define N_EDGES 500000
#define TOT_E   (N_REL * N_EDGES)   // 2,000,000
#define KROW    512             // S row: [S0|S1|S2|S3] halves (x handled separately)

// Device scratch (globals; zero-initialized at load; no runtime allocation)
__device__ __half g_Xs[(size_t)N_PAD * 128];         // x rows fp16 (padded)
__device__ __half g_S[(size_t)N_PAD * KROW];         // aggregated features per node (102MB)
__device__ __half g_Wx[(size_t)128 * 640];           // [W0|W1|W2|W3|Wsl] per out-feature row
__device__ float g_C4[NBINS];                        // per-(node,rel) edge counts
__device__ int g_cnt[NT2];                           // zeroed at load; re-zeroed by scan_final
__device__ int g_off[NT2];
__device__ int g_cursor[NT2];
__device__ int g_part[NBLK2];
__device__ int g_payload[TOT_E];                     // src node per sorted edge

// ---------------------------------------------------------------------------
// helpers
// ---------------------------------------------------------------------------
__device__ __forceinline__ uint32_t smem_u32(const void* p) {
    uint32_t a;
    asm("{ .reg .u64 t; cvta.to.shared.u64 t, %1; cvt.u32.u64 %0, t; }" : "=r"(a) : "l"(p));
    return a;
}
__device__ __forceinline__ void ldsm_x4(uint32_t addr, uint32_t& r0, uint32_t& r1,
                                        uint32_t& r2, uint32_t& r3) {
    asm volatile("ldmatrix.sync.aligned.m8n8.x4.shared.b16 {%0,%1,%2,%3}, [%4];"
                 : "=r"(r0), "=r"(r1), "=r"(r2), "=r"(r3) : "r"(addr));
}
__device__ __forceinline__ void mma16816(float* c, uint32_t a0, uint32_t a1, uint32_t a2,
                                         uint32_t a3, uint32_t b0, uint32_t b1) {
    asm volatile("mma.sync.aligned.m16n8k16.row.col.f32.f16.f16.f32 "
                 "{%0,%1,%2,%3}, {%4,%5,%6,%7}, {%8,%9}, {%0,%1,%2,%3};"
                 : "+f"(c[0]), "+f"(c[1]), "+f"(c[2]), "+f"(c[3])
                 : "r"(a0), "r"(a1), "r"(a2), "r"(a3), "r"(b0), "r"(b1));
}
__device__ __forceinline__ void cp16(uint32_t smem_dst, const void* gsrc) {
    asm volatile("cp.async.cg.shared.global [%0], [%1], 16;"
                 :: "r"(smem_dst), "l"(gsrc));
}

// ---------------------------------------------------------------------------
// conv_x: fp32 x -> fp16 g_Xs rows
// ---------------------------------------------------------------------------
__global__ __launch_bounds__(256) void conv_x_kernel(const float* __restrict__ x) {
    size_t i = (size_t)blockIdx.x * blockDim.x + threadIdx.x;
    if (i >= (size_t)N_NODES * 32) return;
    size_t row = i >> 5;
    int c4 = (int)(i & 31);
    float4 v = reinterpret_cast<const float4*>(x)[i];
    __half h[4];
    h[0] = __float2half_rn(v.x); h[1] = __float2half_rn(v.y);
    h[2] = __float2half_rn(v.z); h[3] = __float2half_rn(v.w);
    *reinterpret_cast<uint2*>(&g_Xs[row * 128 + c4 * 4]) = *reinterpret_cast<uint2*>(h);
}

// conv_w: g_Wx[f][0..639] = [W0[f]|W1[f]|W2[f]|W3[f]|Wsl[f]] fp16
__global__ __launch_bounds__(256) void conv_w_kernel(const float* __restrict__ W,
                                                     const float* __restrict__ Wsl) {
    int i = blockIdx.x * blockDim.x + threadIdx.x;
    if (i >= 128 * 160) return;
    int f = i / 160;
    int c = (i - f * 160) * 4;
    float4 v;
    if (c < 512) {
        int r = c >> 7, dd = c & 127;
        v = *reinterpret_cast<const float4*>(W + (size_t)r * 16384 + (size_t)f * 128 + dd);
    } else {
        v = *reinterpret_cast<const float4*>(Wsl + (size_t)f * 128 + (c - 512));
    }
    __half h[4];
    h[0] = __float2half_rn(v.x); h[1] = __float2half_rn(v.y);
    h[2] = __float2half_rn(v.z); h[3] = __float2half_rn(v.w);
    *reinterpret_cast<uint2*>(&g_Wx[(size_t)f * 640 + c]) = *reinterpret_cast<uint2*>(h);
}

// ---------------------------------------------------------------------------
// Counting sort by key = tgt*4 + rel  (vectorized, 4 edges/thread)
// g_cnt starts zero (load-time init); scan_final re-zeros it after reading,
// so every graph replay sees zeros again. No separate zeroing launch.
// ---------------------------------------------------------------------------
__global__ __launch_bounds__(256) void hist_kernel(const int* __restrict__ EI) {
    int i = blockIdx.x * blockDim.x + threadIdx.x;
    if (i >= TOT_E / 4) return;
    int gq = i * 4;
    int r = gq / N_EDGES;
    int e = gq - r * N_EDGES;
    int4 tg = *reinterpret_cast<const int4*>(EI + (size_t)r * 2 * N_EDGES + N_EDGES + e);
    atomicAdd(&g_cnt[tg.x * 4 + r], 1);
    atomicAdd(&g_cnt[tg.y * 4 + r], 1);
    atomicAdd(&g_cnt[tg.z * 4 + r], 1);
    atomicAdd(&g_cnt[tg.w * 4 + r], 1);
}

__global__ __launch_bounds__(256) void scan_part_kernel() {
    __shared__ int s[256];
    int b = blockIdx.x, t = threadIdx.x;
    int4 v4 = reinterpret_cast<const int4*>(g_cnt)[b * 256 + t];
    s[t] = v4.x + v4.y + v4.z + v4.w;
    __syncthreads();
    for (int off = 128; off > 0; off >>= 1) {
        if (t < off) s[t] += s[t + off];
        __syncthreads();
    }
    if (t == 0) g_part[b] = s[0];
}

__global__ __launch_bounds__(256) void scan_final_kernel() {
    __shared__ int parts[NBLK2];
    __shared__ int s[256];
    int b = blockIdx.x, t = threadIdx.x;
    for (int i = t; i < NBLK2; i += 256) parts[i] = g_part[i];
    __syncthreads();
    int pp = 0;
    for (int i = t; i < b; i += 256) pp += parts[i];
    s[t] = pp;
    __syncthreads();
    for (int off = 128; off > 0; off >>= 1) {
        if (t < off) s[t] += s[t + off];
        __syncthreads();
    }
    const int blockbase = s[0];
    __syncthreads();

    int base = b * 1024 + t * 4;
    int4 e4 = *reinterpret_cast<const int4*>(g_cnt + base);
    // re-zero counts for the next replay (deterministic per-call behavior)
    *reinterpret_cast<int4*>(g_cnt + base) = make_int4(0, 0, 0, 0);
    int e[4] = {e4.x, e4.y, e4.z, e4.w};
    int local[4], sum = 0;
#pragma unroll
    for (int j = 0; j < 4; j++) { local[j] = sum; sum += e[j]; }
    s[t] = sum;
    __syncthreads();
    int own = sum;
    for (int d = 1; d < 256; d <<= 1) {
        int add = (t >= d) ? s[t - d] : 0;
        __syncthreads();
        s[t] += add;
        __syncthreads();
    }
    int baseoff = blockbase + (s[t] - own);
    int4 o4 = make_int4(baseoff + local[0], baseoff + local[1],
                        baseoff + local[2], baseoff + local[3]);
    *reinterpret_cast<int4*>(g_off + base) = o4;
    *reinterpret_cast<int4*>(g_cursor + base) = o4;
}

__global__ __launch_bounds__(256) void reorder_kernel(const int* __restrict__ EI) {
    int i = blockIdx.x * blockDim.x + threadIdx.x;
    if (i >= TOT_E / 4) return;
    int gq = i * 4;
    int r = gq / N_EDGES;
    int e = gq - r * N_EDGES;
    const int* base = EI + (size_t)r * 2 * N_EDGES;
    int4 sr = *reinterpret_cast<const int4*>(base + e);
    int4 tg = *reinterpret_cast<const int4*>(base + N_EDGES + e);
    g_payload[atomicAdd(&g_cursor[tg.x * 4 + r], 1)] = sr.x;
    g_payload[atomicAdd(&g_cursor[tg.y * 4 + r], 1)] = sr.y;
    g_payload[atomicAdd(&g_cursor[tg.z * 4 + r], 1)] = sr.z;
    g_payload[atomicAdd(&g_cursor[tg.w * 4 + r], 1)] = sr.w;
}

// ---------------------------------------------------------------------------
// Gather: one warp per (target,rel) BIN. k = t*4+r. Mean 5 edges/bin.
// Half-warp per edge (16 lanes x 16B), two edges per step. (Round-10 proven.)
// ---------------------------------------------------------------------------
__global__ __launch_bounds__(256) void gather_kernel() {
    const int k = blockIdx.x * 8 + (threadIdx.x >> 5);
    if (k >= NBINS) return;
    const int lane = threadIdx.x & 31;
    const int group = lane >> 4;
    const int sub = lane & 15;

    const int beg = g_off[k];
    const int end = g_off[k + 1];

    float acc[8];
#pragma unroll
    for (int i = 0; i < 8; i++) acc[i] = 0.0f;

    for (int base = beg; base < end; base += 32) {
        int i = base + lane;
        int p = (i < end) ? g_payload[i] : 0;
        int m = min(end - base, 32);
        for (int j = 0; j < m; j += 2) {
            int jj = j + group;
            int src = __shfl_sync(0xffffffffu, p, min(jj, m - 1));
            if (jj < m) {
                uint4 raw = *reinterpret_cast<const uint4*>(
                    g_Xs + (size_t)src * 128 + sub * 8);
                const __half2* h2 = reinterpret_cast<const __half2*>(&raw);
#pragma unroll
                for (int q = 0; q < 4; q++) {
                    float2 f = __half22float2(h2[q]);
                    acc[q * 2 + 0] += f.x;
                    acc[q * 2 + 1] += f.y;
                }
            }
        }
    }
#pragma unroll
    for (int i = 0; i < 8; i++) acc[i] += __shfl_xor_sync(0xffffffffu, acc[i], 16);

    if (group == 0) {
        const int t = k >> 2;
        const int r = k & 3;
        __half h[8];
#pragma unroll
        for (int q = 0; q < 8; q++) h[q] = __float2half_rn(acc[q]);
        *reinterpret_cast<uint4*>(&g_S[(size_t)t * KROW + r * 128 + sub * 8]) =
            *reinterpret_cast<uint4*>(h);
    }
    if (lane == 0) g_C4[k] = (float)(end - beg);
}

// ---------------------------------------------------------------------------
// GEMM (cp.async double-buffered): out = [S|x] @ Wx^T + Sum_r C4*b_r + bsl
// K=640: steps 0..7 read g_S (512 cols), steps 8..9 read g_Xs (128 cols).
// ---------------------------------------------------------------------------
__global__ __launch_bounds__(256, 2) void gemm_mma_kernel(const float* __restrict__ b,
                                                          const float* __restrict__ bsl,
                                                          float* __restrict__ out) {
    extern __shared__ __half smem[];
    const int tid = threadIdx.x;
    const int lane = tid & 31;
    const int wid = tid >> 5;
    const int wm = wid & 3;
    const int wn = wid >> 2;
    const int m0 = blockIdx.x * 128;

    float acc[2][8][4];
#pragma unroll
    for (int i = 0; i < 2; i++)
#pragma unroll
        for (int j = 0; j < 8; j++)
#pragma unroll
            for (int k = 0; k < 4; k++) acc[i][j][k] = 0.0f;

    const uint32_t sAu = smem_u32(smem);
    const uint32_t sBu = sAu + 2 * 16384;

    auto load_tiles = [&](int buf, int step) {
        const int kc = step * 64;
#pragma unroll
        for (int it = 0; it < 4; it++) {
            int idx = tid + it * 256;
            int row = idx >> 3;
            int ch = idx & 7;
            int sw = (ch ^ (row & 7)) << 4;
            const __half* srcA = (kc < 512)
                ? (g_S + (size_t)(m0 + row) * KROW + kc + ch * 8)
                : (g_Xs + (size_t)(m0 + row) * 128 + (kc - 512) + ch * 8);
            cp16(sAu + buf * 16384 + row * 128 + sw, srcA);
            cp16(sBu + buf * 16384 + row * 128 + sw,
                 g_Wx + (size_t)row * 640 + kc + ch * 8);
        }
        asm volatile("cp.async.commit_group;");
    };

    load_tiles(0, 0);

#pragma unroll 1
    for (int step = 0; step < 10; step++) {
        if (step < 9) {
            load_tiles((step + 1) & 1, step + 1);
            asm volatile("cp.async.wait_group 1;");
        } else {
            asm volatile("cp.async.wait_group 0;");
        }
        __syncthreads();

        const int boff = (step & 1) * 16384;
#pragma unroll
        for (int kq = 0; kq < 4; kq++) {
            uint32_t a[2][4];
#pragma unroll
            for (int mf = 0; mf < 2; mf++) {
                int row = wm * 32 + mf * 16 + (lane & 15);
                int kch = kq * 2 + (lane >> 4);
                uint32_t addr = sAu + boff + row * 128 + ((kch ^ (row & 7)) << 4);
                ldsm_x4(addr, a[mf][0], a[mf][1], a[mf][2], a[mf][3]);
            }
            uint32_t bb[8][2];
#pragma unroll
            for (int np = 0; np < 4; np++) {
                int n = wn * 64 + np * 16 + ((lane >> 4) << 3) + (lane & 7);
                int kch = kq * 2 + ((lane >> 3) & 1);
                uint32_t addr = sBu + boff + n * 128 + ((kch ^ (n & 7)) << 4);
                ldsm_x4(addr, bb[np * 2][0], bb[np * 2][1], bb[np * 2 + 1][0], bb[np * 2 + 1][1]);
            }
#pragma unroll
            for (int mf = 0; mf < 2; mf++)
#pragma unroll
                for (int nf = 0; nf < 8; nf++)
                    mma16816(acc[mf][nf], a[mf][0], a[mf][1], a[mf][2], a[mf][3],
                             bb[nf][0], bb[nf][1]);
        }
        __syncthreads();
    }

    const int r0 = lane >> 2;
    const int c0 = (lane & 3) * 2;
#pragma unroll
    for (int mf = 0; mf < 2; mf++) {
#pragma unroll
        for (int half = 0; half < 2; half++) {
            int gm = m0 + wm * 32 + mf * 16 + r0 + half * 8;
            if (gm >= N_NODES) continue;
            float4 c4 = *reinterpret_cast<const float4*>(g_C4 + (size_t)gm * 4);
            float* dst = out + (size_t)gm * 128 + wn * 64 + c0;
#pragma unroll
            for (int nf = 0; nf < 8; nf++) {
                int col = wn * 64 + c0 + nf * 8;
                float2 b0 = *reinterpret_cast<const float2*>(b + 0 * 128 + col);
                float2 b1 = *reinterpret_cast<const float2*>(b + 1 * 128 + col);
                float2 b2 = *reinterpret_cast<const float2*>(b + 2 * 128 + col);
                float2 b3 = *reinterpret_cast<const float2*>(b + 3 * 128 + col);
                float2 bs = *reinterpret_cast<const float2*>(bsl + col);
                float2 v;
                v.x = acc[mf][nf][half * 2] +
                      c4.x * b0.x + c4.y * b1.x + c4.z * b2.x + c4.w * b3.x + bs.x;
                v.y = acc[mf][nf][half * 2 + 1] +
                      c4.x * b0.y + c4.y * b1.y + c4.z * b2.y + c4.w * b3.y + bs.y;
                *reinterpret_cast<float2*>(dst + nf * 8) = v;
            }
        }
    }
}

// ---------------------------------------------------------------------------
extern "C" void kernel_launch(void* const* d_in, const int* in_sizes, int n_in,
                              void* d_out, int out_size) {
    const float* x   = (const float*)d_in[0];
    const int*   ei  = (const int*)  d_in[1];
    const float* W   = (const float*)d_in[2];
    const float* b   = (const float*)d_in[3];
    const float* Wsl = (const float*)d_in[4];
    const float* bsl = (const float*)d_in[5];
    float* out = (float*)d_out;

    const int GEMM_SMEM = 4 * 128 * 64 * (int)sizeof(__half);  // 64 KB

    static cudaStream_t s2 = nullptr;
    static cudaEvent_t ev_fork = nullptr, ev_convx = nullptr, ev_join = nullptr;
    static bool overlap_ok = false;
    static bool attr_done = false;
    if (!attr_done) {
        cudaFuncSetAttribute(gemm_mma_kernel,
                             cudaFuncAttributeMaxDynamicSharedMemorySize, GEMM_SMEM);
        attr_done = true;
    }
    if (!s2) {
        overlap_ok =
            (cudaStreamCreateWithFlags(&s2, cudaStreamNonBlocking) == cudaSuccess) &&
            (cudaEventCreateWithFlags(&ev_fork, cudaEventDisableTiming) == cudaSuccess) &&
            (cudaEventCreateWithFlags(&ev_convx, cudaEventDisableTiming) == cudaSuccess) &&
            (cudaEventCreateWithFlags(&ev_join, cudaEventDisableTiming) == cudaSuccess);
    }

    if (!overlap_ok) {
        conv_x_kernel<<<(N_NODES * 32 + 255) / 256, 256>>>(x);
        conv_w_kernel<<<(128 * 160 + 255) / 256, 256>>>(W, Wsl);
        hist_kernel<<<(TOT_E / 4 + 255) / 256, 256>>>(ei);
        scan_part_kernel<<<NBLK2, 256>>>();
        scan_final_kernel<<<NBLK2, 256>>>();
        reorder_kernel<<<(TOT_E / 4 + 255) / 256, 256>>>(ei);
        gather_kernel<<<NBINS / 8, 256>>>();
        gemm_mma_kernel<<<782, 256, GEMM_SMEM>>>(b, bsl, out);
        return;
    }

    // fork
    cudaEventRecord(ev_fork, 0);
    cudaStreamWaitEvent(s2, ev_fork, 0);

    // Stream 0: conversions
    conv_x_kernel<<<(N_NODES * 32 + 255) / 256, 256>>>(x);
    cudaEventRecord(ev_convx, 0);
    conv_w_kernel<<<(128 * 160 + 255) / 256, 256>>>(W, Wsl);

    // Stream B: counting sort, then gather (needs g_Xs)
    hist_kernel<<<(TOT_E / 4 + 255) / 256, 256, 0, s2>>>(ei);
    scan_part_kernel<<<NBLK2, 256, 0, s2>>>();
    scan_final_kernel<<<NBLK2, 256, 0, s2>>>();
    reorder_kernel<<<(TOT_E / 4 + 255) / 256, 256, 0, s2>>>(ei);
    cudaStreamWaitEvent(s2, ev_convx, 0);
    gather_kernel<<<NBINS / 8, 256, 0, s2>>>();
    cudaEventRecord(ev_join, s2);

    // Stream 0: single fused GEMM after gather
    cudaStreamWaitEvent(0, ev_join, 0);
    gemm_mma_kernel<<<782, 256, GEMM_SMEM, 0>>>(b, bsl, out);
}